// round 1
// baseline (speedup 1.0000x reference)
#include <cuda_runtime.h>

#define BB 512
#define FF 64
#define LL 400
#define EE 8
#define TT 4
#define C1C 64
#define C2C 16
#define KK 3
#define UU 6400
#define FL 25600
#define LC 100
#define XS_W 108   // 106 valid + pad
#define H1_W 105   // 104 valid + pad

// scratch (static device allocations are allowed; cudaMalloc is not)
__device__ float g_expert_out[(size_t)EE * BB * UU];   // ~104.9 MB
__device__ float g_gates[TT * BB * EE];

// ---------------------------------------------------------------------------
// Kernel 1: gates. [B, 25600] x [25600, T*E] -> softmax over E.
// Block = 4 batch rows; warp w: t = w/2, half = w%2; lane = (fo = lane/8, e = lane%8)
// ---------------------------------------------------------------------------
__global__ void __launch_bounds__(256) gates_kernel(
    const float* __restrict__ x, const float* __restrict__ gk,
    const float* __restrict__ gbias) {
  __shared__ float xs[4 * 2560];
  __shared__ float part[8 * 4 * 8];
  int tid = threadIdx.x;
  int b0 = blockIdx.x * 4;
  int w = tid >> 5, lane = tid & 31;
  int t = w >> 1, half = w & 1;
  int fo = lane >> 3, e = lane & 7;
  float acc[4] = {0.f, 0.f, 0.f, 0.f};

  for (int c = 0; c < 10; c++) {
    __syncthreads();
    for (int idx = tid; idx < 4 * 2560; idx += 256) {
      int bi = idx / 2560, j = idx % 2560;
      xs[idx] = x[(size_t)(b0 + bi) * FL + c * 2560 + j];
    }
    __syncthreads();
    int lf0 = half * 1280;
    const float* gkt = gk + ((size_t)t * FL + (size_t)c * 2560) * EE;
#pragma unroll 4
    for (int lf = lf0; lf < lf0 + 1280; lf += 4) {
      float wv = gkt[(lf + fo) * EE + e];
      acc[0] += xs[0 * 2560 + lf + fo] * wv;
      acc[1] += xs[1 * 2560 + lf + fo] * wv;
      acc[2] += xs[2 * 2560 + lf + fo] * wv;
      acc[3] += xs[3 * 2560 + lf + fo] * wv;
    }
  }
#pragma unroll
  for (int bi = 0; bi < 4; bi++) {
    acc[bi] += __shfl_down_sync(0xffffffffu, acc[bi], 8);
    acc[bi] += __shfl_down_sync(0xffffffffu, acc[bi], 16);
  }
  if (lane < 8) {
#pragma unroll
    for (int bi = 0; bi < 4; bi++) part[(w * 4 + bi) * 8 + lane] = acc[bi];
  }
  __syncthreads();
  if (tid < 16) {
    int tt = tid >> 2, bi = tid & 3;
    float v[8];
    float mx = -1e30f;
#pragma unroll
    for (int ee = 0; ee < 8; ee++) {
      v[ee] = part[((tt * 2) * 4 + bi) * 8 + ee] +
              part[((tt * 2 + 1) * 4 + bi) * 8 + ee] + gbias[tt * 8 + ee];
      mx = fmaxf(mx, v[ee]);
    }
    float s = 0.f;
#pragma unroll
    for (int ee = 0; ee < 8; ee++) { v[ee] = expf(v[ee] - mx); s += v[ee]; }
    float inv = 1.f / s;
#pragma unroll
    for (int ee = 0; ee < 8; ee++)
      g_gates[((size_t)tt * BB + b0 + bi) * EE + ee] = v[ee] * inv;
  }
}

// ---------------------------------------------------------------------------
// Kernel 2: fused TCN experts. Block = (b, e, L-chunk of 100).
// conv1 (dil 1, causal pad 2) -> relu -> conv2 (dil 2, causal pad 4) -> relu
// -> +expert_bias -> relu -> scratch
// ---------------------------------------------------------------------------
__global__ void __launch_bounds__(256) expert_kernel(
    const float* __restrict__ x, const float* __restrict__ w1,
    const float* __restrict__ b1, const float* __restrict__ w2,
    const float* __restrict__ b2, const float* __restrict__ ebias) {
  extern __shared__ float sm[];
  float* xs  = sm;                    // 64*108
  float* w1s = xs + 64 * XS_W;        // 64*193
  float* h1s = w1s + 64 * 193;        // 64*105
  float* w2s = h1s + 64 * H1_W;       // 16*193
  float* h2s = w2s + 16 * 193;        // 16*100

  int tid = threadIdx.x;
  int bx = blockIdx.x;
  int b = bx >> 5;
  int r = bx & 31;
  int e = r >> 2;
  int chunk = r & 3;
  int l0 = chunk * LC;

  // stage x slab [64][l0-6 .. l0+99], zero-filled left pad
  const float* xb = x + (size_t)b * FF * LL;
  for (int idx = tid; idx < 64 * 106; idx += 256) {
    int f = idx / 106, i = idx % 106;
    int gl = l0 - 6 + i;
    xs[f * XS_W + i] = (gl >= 0) ? xb[f * LL + gl] : 0.f;
  }
  const float* w1e = w1 + (size_t)e * C1C * FF * KK;
  for (int idx = tid; idx < C1C * FF * KK; idx += 256)
    w1s[(idx / 192) * 193 + (idx % 192)] = w1e[idx];
  const float* w2e = w2 + (size_t)e * C2C * C1C * KK;
  for (int idx = tid; idx < C2C * C1C * KK; idx += 256)
    w2s[(idx / 192) * 193 + (idx % 192)] = w2e[idx];
  __syncthreads();

  // conv1: thread = (c1 = tid%64, lg = tid/64); 26 l-positions each (104 total
  // = LC + 4 halo for dilated conv2)
  {
    int c = tid & 63, lg = tid >> 6;
    int m0 = lg * 26;
    float acc[26];
#pragma unroll
    for (int j = 0; j < 26; j++) acc[j] = 0.f;
    const float* wr = w1s + c * 193;
    for (int f = 0; f < FF; f++) {
      float xw[28];
#pragma unroll
      for (int j = 0; j < 28; j++) xw[j] = xs[f * XS_W + m0 + j];
#pragma unroll
      for (int k = 0; k < 3; k++) {
        float wv = wr[f * 3 + k];
#pragma unroll
        for (int j = 0; j < 26; j++) acc[j] += xw[j + k] * wv;
      }
    }
    float bb = b1[e * C1C + c];
#pragma unroll
    for (int j = 0; j < 26; j++) {
      int m = m0 + j;
      int gl = l0 - 4 + m;  // causal: h1 at global l<0 is zero padding
      h1s[c * H1_W + m] = (gl >= 0) ? fmaxf(acc[j] + bb, 0.f) : 0.f;
    }
  }
  __syncthreads();

  // conv2 (dilation 2): thread = (c2 = tid%16, lg2 = tid/16); l = lg2 + 16*j
  {
    int c2 = tid & 15, lg2 = tid >> 4;
    float acc2[7];
#pragma unroll
    for (int j = 0; j < 7; j++) acc2[j] = 0.f;
    const float* wr = w2s + c2 * 193;
    for (int c1i = 0; c1i < C1C; c1i++) {
      const float* hr = h1s + c1i * H1_W + lg2;
#pragma unroll
      for (int k = 0; k < 3; k++) {
        float wv = wr[c1i * 3 + k];
#pragma unroll
        for (int j = 0; j < 6; j++) acc2[j] += hr[16 * j + 2 * k] * wv;
        if (lg2 < 4) acc2[6] += hr[96 + 2 * k] * wv;
      }
    }
    float bb = b2[e * C2C + c2];
#pragma unroll
    for (int j = 0; j < 7; j++) {
      int l = lg2 + 16 * j;
      if (l < LC) h2s[c2 * LC + l] = fmaxf(acc2[j] + bb, 0.f);
    }
  }
  __syncthreads();

  // bias + relu + coalesced store
  {
    const float* eb = ebias + (size_t)e * UU;
    float* eo = g_expert_out + ((size_t)(e * BB + b)) * UU;
    for (int idx = tid; idx < C2C * LC; idx += 256) {
      int c2i = idx / LC, l = idx % LC;
      int u = c2i * LL + l0 + l;
      eo[u] = fmaxf(h2s[idx] + eb[u], 0.f);
    }
  }
}

// ---------------------------------------------------------------------------
// Kernel 3: gated mixture. out[t,b,u] = sum_e g[t,b,e]*eo[e,b,u] + task_bias[t]
// ---------------------------------------------------------------------------
__global__ void __launch_bounds__(256) mix_kernel(
    const float* __restrict__ tbias, float* __restrict__ out) {
  __shared__ float gsh[TT * EE];
  int b = blockIdx.x;
  int tid = threadIdx.x;
  if (tid < TT * EE)
    gsh[tid] = g_gates[((size_t)(tid >> 3) * BB + b) * EE + (tid & 7)];
  __syncthreads();
  int u4 = (blockIdx.y * 256 + tid) * 4;
  if (u4 >= UU) return;

  float4 a[TT];
#pragma unroll
  for (int t = 0; t < TT; t++) {
    float tb = tbias[t];
    a[t] = make_float4(tb, tb, tb, tb);
  }
#pragma unroll
  for (int e = 0; e < EE; e++) {
    float4 v = *reinterpret_cast<const float4*>(
        g_expert_out + ((size_t)(e * BB + b)) * UU + u4);
#pragma unroll
    for (int t = 0; t < TT; t++) {
      float g = gsh[t * 8 + e];
      a[t].x += g * v.x;
      a[t].y += g * v.y;
      a[t].z += g * v.z;
      a[t].w += g * v.w;
    }
  }
#pragma unroll
  for (int t = 0; t < TT; t++)
    *reinterpret_cast<float4*>(out + ((size_t)(t * BB + b)) * UU + u4) = a[t];
}

// ---------------------------------------------------------------------------
extern "C" void kernel_launch(void* const* d_in, const int* in_sizes, int n_in,
                              void* d_out, int out_size) {
  const float* x  = (const float*)d_in[0];
  const float* w1 = (const float*)d_in[1];
  const float* b1 = (const float*)d_in[2];
  const float* w2 = (const float*)d_in[3];
  const float* b2 = (const float*)d_in[4];
  const float* eb = (const float*)d_in[5];
  const float* gk = (const float*)d_in[6];
  const float* gb = (const float*)d_in[7];
  const float* tb = (const float*)d_in[8];
  float* out = (float*)d_out;

  const int smem_bytes =
      (64 * XS_W + 64 * 193 + 64 * H1_W + 16 * 193 + 16 * LC) * 4;  // 122688
  cudaFuncSetAttribute(expert_kernel,
                       cudaFuncAttributeMaxDynamicSharedMemorySize, smem_bytes);

  gates_kernel<<<BB / 4, 256>>>(x, gk, gb);
  expert_kernel<<<EE * BB * 4, 256, smem_bytes>>>(x, w1, b1, w2, b2, eb);
  mix_kernel<<<dim3(BB, 7), 256>>>(tb, out);
}

// round 2
// speedup vs baseline: 2.3737x; 2.3737x over previous
#include <cuda_runtime.h>

#define BB 512
#define FF 64
#define LL 400
#define EE 8
#define TT 4
#define C1C 64
#define C2C 16
#define KK 3
#define UU 6400
#define FL 25600
#define LC 100
#define XS_W 108   // 106 valid + pad (even, keeps 8B alignment)
#define H1_W 105

// scratch (static device allocations are allowed; cudaMalloc is not)
__device__ float g_expert_out[(size_t)EE * BB * UU];   // ~104.9 MB
__device__ float g_gates[TT * BB * EE];
__device__ float g_part[4 * TT * BB * EE];             // 4 f-segments of partial gate logits

// ---------- f32x2 packed helpers (PTX-only on sm_10x) ----------
__device__ __forceinline__ unsigned long long pk2(float lo, float hi) {
  unsigned long long r;
  asm("mov.b64 %0, {%1, %2};" : "=l"(r) : "f"(lo), "f"(hi));
  return r;
}
__device__ __forceinline__ void fma2(unsigned long long& d, unsigned long long a,
                                     unsigned long long b) {
  asm("fma.rn.f32x2 %0, %1, %2, %0;" : "+l"(d) : "l"(a), "l"(b));
}
__device__ __forceinline__ float2 upk(unsigned long long v) {
  float2 f;
  asm("mov.b64 {%0, %1}, %2;" : "=f"(f.x), "=f"(f.y) : "l"(v));
  return f;
}

// ---------------------------------------------------------------------------
// Kernel 1: gate logits, f-split into 4 segments of 6400.
// Block = 4 batch rows x 1 segment. Warp w: t=w/2, half=w%2.
// Lane: fo=lane>>2 (f offset 0..7), ep=lane&3 (expert pair -> e=2ep,2ep+1).
// ---------------------------------------------------------------------------
__global__ void __launch_bounds__(256) gates_kernel(
    const float* __restrict__ x, const float* __restrict__ gk) {
  __shared__ float xs[4 * 1280];
  __shared__ float part[8][4][8];
  int tid = threadIdx.x;
  int b0 = blockIdx.x * 4;
  int seg = blockIdx.y;
  int w = tid >> 5, lane = tid & 31;
  int t = w >> 1, half = w & 1;
  int fo = lane >> 2, ep = lane & 3;

  float acc[4][2];
#pragma unroll
  for (int bi = 0; bi < 4; bi++) { acc[bi][0] = 0.f; acc[bi][1] = 0.f; }

  for (int c = 0; c < 5; c++) {
    __syncthreads();
    for (int idx = tid; idx < 4 * 1280; idx += 256) {
      int bi = idx >> 10 | 0;  // idx/1280 below
      bi = idx / 1280;
      int j = idx - bi * 1280;
      xs[idx] = x[(size_t)(b0 + bi) * FL + seg * 6400 + c * 1280 + j];
    }
    __syncthreads();
    int lf0 = half * 640;
    const float2* gk2 = reinterpret_cast<const float2*>(
        gk + ((size_t)t * FL + (size_t)seg * 6400 + c * 1280 + lf0) * EE);
#pragma unroll 4
    for (int i = 0; i < 80; i++) {
      int f = i * 8 + fo;
      float2 wv = gk2[f * 4 + ep];
      float x0 = xs[0 * 1280 + lf0 + f];
      float x1 = xs[1 * 1280 + lf0 + f];
      float x2 = xs[2 * 1280 + lf0 + f];
      float x3 = xs[3 * 1280 + lf0 + f];
      acc[0][0] += x0 * wv.x; acc[0][1] += x0 * wv.y;
      acc[1][0] += x1 * wv.x; acc[1][1] += x1 * wv.y;
      acc[2][0] += x2 * wv.x; acc[2][1] += x2 * wv.y;
      acc[3][0] += x3 * wv.x; acc[3][1] += x3 * wv.y;
    }
  }
  // reduce over fo (lane bits 2..4)
#pragma unroll
  for (int bi = 0; bi < 4; bi++)
#pragma unroll
    for (int j = 0; j < 2; j++) {
      acc[bi][j] += __shfl_xor_sync(0xffffffffu, acc[bi][j], 4);
      acc[bi][j] += __shfl_xor_sync(0xffffffffu, acc[bi][j], 8);
      acc[bi][j] += __shfl_xor_sync(0xffffffffu, acc[bi][j], 16);
    }
  if (lane < 4) {
#pragma unroll
    for (int bi = 0; bi < 4; bi++) {
      part[w][bi][2 * ep] = acc[bi][0];
      part[w][bi][2 * ep + 1] = acc[bi][1];
    }
  }
  __syncthreads();
  if (tid < 128) {
    int tt = tid >> 5, bi = (tid >> 3) & 3, e = tid & 7;
    float s = part[tt * 2][bi][e] + part[tt * 2 + 1][bi][e];
    g_part[(((size_t)seg * TT + tt) * BB + b0 + bi) * EE + e] = s;
  }
}

// ---------------------------------------------------------------------------
// Kernel 1b: reduce segments + softmax
// ---------------------------------------------------------------------------
__global__ void __launch_bounds__(256) finalize_gates(
    const float* __restrict__ gbias) {
  int gid = blockIdx.x * 256 + threadIdx.x;
  if (gid >= TT * BB) return;
  int t = gid >> 9, b = gid & 511;
  float v[8];
  float mx = -1e30f;
#pragma unroll
  for (int e = 0; e < 8; e++) {
    float s = gbias[t * 8 + e];
#pragma unroll
    for (int sg = 0; sg < 4; sg++)
      s += g_part[(((size_t)sg * TT + t) * BB + b) * EE + e];
    v[e] = s;
    mx = fmaxf(mx, s);
  }
  float sum = 0.f;
#pragma unroll
  for (int e = 0; e < 8; e++) { v[e] = expf(v[e] - mx); sum += v[e]; }
  float inv = 1.f / sum;
#pragma unroll
  for (int e = 0; e < 8; e++)
    g_gates[((size_t)t * BB + b) * EE + e] = v[e] * inv;
}

// ---------------------------------------------------------------------------
// Kernel 2: fused TCN experts with packed f32x2 math.
// Block = (b, e, L-chunk of 100). smem overlaid: w2/h2 reuse the x slab.
// conv1 thread map: c32 = tid&31 (channels c32, c32+32), lg = tid>>5, 13 l each.
// ---------------------------------------------------------------------------
__global__ void __launch_bounds__(256, 2) expert_kernel(
    const float* __restrict__ x, const float* __restrict__ w1,
    const float* __restrict__ b1, const float* __restrict__ w2,
    const float* __restrict__ b2, const float* __restrict__ ebias) {
  extern __shared__ float sm[];
  float* xs  = sm;                    // 64*108 = 6912 floats (reused later)
  float* w1s = xs + 64 * XS_W;        // 64*193 = 12352
  float* h1s = w1s + 64 * 193;        // 64*105 = 6720
  float* w2s = xs;                    // overlay: 16*193 = 3088
  float* h2s = xs + 16 * 193;         // overlay: 16*100 = 1600

  int tid = threadIdx.x;
  int bx = blockIdx.x;
  int b = bx >> 5;
  int r = bx & 31;
  int e = r >> 2;
  int chunk = r & 3;
  int l0 = chunk * LC;

  // stage x slab [64][l0-6 .. l0+99] and w1
  const float* xb = x + (size_t)b * FF * LL;
  for (int idx = tid; idx < 64 * 106; idx += 256) {
    int f = idx / 106, i = idx - f * 106;
    int gl = l0 - 6 + i;
    xs[f * XS_W + i] = (gl >= 0) ? xb[f * LL + gl] : 0.f;
  }
  const float* w1e = w1 + (size_t)e * C1C * FF * KK;
  for (int idx = tid; idx < C1C * FF * KK; idx += 256)
    w1s[(idx / 192) * 193 + (idx % 192)] = w1e[idx];
  __syncthreads();

  // ---- conv1 (dil 1), packed over channel pair (c32, c32+32) ----
  {
    int c32 = tid & 31, lg = tid >> 5;
    int m0 = lg * 13;
    unsigned long long acc[13];
#pragma unroll
    for (int j = 0; j < 13; j++) acc[j] = 0ull;
    const float* wlo = w1s + c32 * 193;
    const float* whi = w1s + (c32 + 32) * 193;
#pragma unroll 2
    for (int f = 0; f < FF; f++) {
      unsigned long long W[15];
#pragma unroll
      for (int j = 0; j < 15; j++) {
        float xv = xs[f * XS_W + m0 + j];
        W[j] = pk2(xv, xv);
      }
#pragma unroll
      for (int k = 0; k < 3; k++) {
        unsigned long long wv = pk2(wlo[f * 3 + k], whi[f * 3 + k]);
#pragma unroll
        for (int j = 0; j < 13; j++) fma2(acc[j], W[j + k], wv);
      }
    }
    float bl = b1[e * C1C + c32];
    float bh = b1[e * C1C + c32 + 32];
#pragma unroll
    for (int j = 0; j < 13; j++) {
      int m = m0 + j;
      int gl = l0 - 4 + m;  // causal: h1 at global l<0 is zero
      float2 v = upk(acc[j]);
      h1s[c32 * H1_W + m]        = (gl >= 0) ? fmaxf(v.x + bl, 0.f) : 0.f;
      h1s[(c32 + 32) * H1_W + m] = (gl >= 0) ? fmaxf(v.y + bh, 0.f) : 0.f;
    }
  }
  __syncthreads();

  // stage w2 into the (now dead) x slab region
  const float* w2e = w2 + (size_t)e * C2C * C1C * KK;
  for (int idx = tid; idx < C2C * C1C * KK; idx += 256)
    w2s[(idx / 192) * 193 + (idx % 192)] = w2e[idx];
  __syncthreads();

  // ---- conv2 (dilation 2), scalar ----
  {
    int c2 = tid & 15, lg2 = tid >> 4;
    float acc2[7];
#pragma unroll
    for (int j = 0; j < 7; j++) acc2[j] = 0.f;
    const float* wr = w2s + c2 * 193;
#pragma unroll 2
    for (int c1i = 0; c1i < C1C; c1i++) {
      const float* hr = h1s + c1i * H1_W + lg2;
#pragma unroll
      for (int k = 0; k < 3; k++) {
        float wv = wr[c1i * 3 + k];
#pragma unroll
        for (int j = 0; j < 6; j++) acc2[j] += hr[16 * j + 2 * k] * wv;
        if (lg2 < 4) acc2[6] += hr[96 + 2 * k] * wv;
      }
    }
    float bb = b2[e * C2C + c2];
#pragma unroll
    for (int j = 0; j < 7; j++) {
      int l = lg2 + 16 * j;
      if (l < LC) h2s[c2 * LC + l] = fmaxf(acc2[j] + bb, 0.f);
    }
  }
  __syncthreads();

  // ---- bias + relu + coalesced store ----
  {
    const float* eb = ebias + (size_t)e * UU;
    float* eo = g_expert_out + ((size_t)(e * BB + b)) * UU;
    for (int idx = tid; idx < C2C * LC; idx += 256) {
      int c2i = idx / LC, l = idx - c2i * LC;
      int u = c2i * LL + l0 + l;
      eo[u] = fmaxf(h2s[idx] + eb[u], 0.f);
    }
  }
}

// ---------------------------------------------------------------------------
// Kernel 3: gated mixture. out[t,b,u] = sum_e g[t,b,e]*eo[e,b,u] + task_bias[t]
// ---------------------------------------------------------------------------
__global__ void __launch_bounds__(256) mix_kernel(
    const float* __restrict__ tbias, float* __restrict__ out) {
  __shared__ float gsh[TT * EE];
  int b = blockIdx.x;
  int tid = threadIdx.x;
  if (tid < TT * EE)
    gsh[tid] = g_gates[((size_t)(tid >> 3) * BB + b) * EE + (tid & 7)];
  __syncthreads();
  int u4 = (blockIdx.y * 256 + tid) * 4;
  if (u4 >= UU) return;

  float4 a[TT];
#pragma unroll
  for (int t = 0; t < TT; t++) {
    float tb = tbias[t];
    a[t] = make_float4(tb, tb, tb, tb);
  }
#pragma unroll
  for (int e = 0; e < EE; e++) {
    float4 v = *reinterpret_cast<const float4*>(
        g_expert_out + ((size_t)(e * BB + b)) * UU + u4);
#pragma unroll
    for (int t = 0; t < TT; t++) {
      float g = gsh[t * 8 + e];
      a[t].x += g * v.x;
      a[t].y += g * v.y;
      a[t].z += g * v.z;
      a[t].w += g * v.w;
    }
  }
#pragma unroll
  for (int t = 0; t < TT; t++)
    *reinterpret_cast<float4*>(out + ((size_t)(t * BB + b)) * UU + u4) = a[t];
}

// ---------------------------------------------------------------------------
extern "C" void kernel_launch(void* const* d_in, const int* in_sizes, int n_in,
                              void* d_out, int out_size) {
  const float* x  = (const float*)d_in[0];
  const float* w1 = (const float*)d_in[1];
  const float* b1 = (const float*)d_in[2];
  const float* w2 = (const float*)d_in[3];
  const float* b2 = (const float*)d_in[4];
  const float* eb = (const float*)d_in[5];
  const float* gk = (const float*)d_in[6];
  const float* gb = (const float*)d_in[7];
  const float* tb = (const float*)d_in[8];
  float* out = (float*)d_out;

  const int smem_bytes = (64 * XS_W + 64 * 193 + 64 * H1_W) * 4;  // 103936
  cudaFuncSetAttribute(expert_kernel,
                       cudaFuncAttributeMaxDynamicSharedMemorySize, smem_bytes);

  expert_kernel<<<EE * BB * 4, 256, smem_bytes>>>(x, w1, b1, w2, b2, eb);
  gates_kernel<<<dim3(BB / 4, 4), 256>>>(x, gk);
  finalize_gates<<<8, 256>>>(gb);
  mix_kernel<<<dim3(BB, 7), 256>>>(tb, out);
}

// round 7
// speedup vs baseline: 3.8111x; 1.6056x over previous
#include <cuda_runtime.h>
#include <cstdint>

#define BB 512
#define FF 64
#define LL 400
#define EE 8
#define TT 4
#define C1C 64
#define C2C 16
#define UU 6400
#define FL 25600

// scratch
__device__ float g_expert_out[(size_t)EE * BB * UU];   // ~104.9 MB
__device__ float g_gates[TT * BB * EE];
__device__ float g_part[4 * TT * BB * EE];

// ---------- helpers ----------
__device__ __forceinline__ uint32_t f2tf32(float f) {
  uint32_t u;
  asm("cvt.rna.tf32.f32 %0, %1;" : "=r"(u) : "f"(f));
  return u;
}
__device__ __forceinline__ void mma_tf32(float* c, uint32_t a0, uint32_t a1,
                                         uint32_t a2, uint32_t a3, uint32_t b0,
                                         uint32_t b1) {
  asm volatile(
      "mma.sync.aligned.m16n8k8.row.col.f32.tf32.tf32.f32 "
      "{%0,%1,%2,%3}, {%4,%5,%6,%7}, {%8,%9}, {%0,%1,%2,%3};"
      : "+f"(c[0]), "+f"(c[1]), "+f"(c[2]), "+f"(c[3])
      : "r"(a0), "r"(a1), "r"(a2), "r"(a3), "r"(b0), "r"(b1));
}

// smem layout (floats)
#define XS_OFF 0
#define XS_STR 212      // cols 0..209 = x[l0-6 .. l0+203]
#define W1_OFF 13568    // [64][196]
#define H1_OFF 26112    // transposed h1: [212 rows][stride 68], row r = l-(l0-4)
#define H1_STR 68
#define W2_OFF 40528    // [16][196]
#define SMEM_FLOATS 43664
#define SMEM_BYTES (SMEM_FLOATS * 4)   // 174656

// ---------------------------------------------------------------------------
// Expert kernel: warp-level tf32 MMA. Block = (e, b); 2 chunks of M=208.
// conv1: D1[208,64] = A1[208,192(q=f*3+k)] x W1[64,192]  (A1[r][q]=x[f][l0-6+r+k])
// conv2: D2[208,16] = A2[208,192(q=c1*3+k)] x W2[16,192] (A2[m][q]=h1t[m+2k][c1])
// ---------------------------------------------------------------------------
__global__ void __launch_bounds__(256, 1) expert_mma_kernel(
    const float* __restrict__ x, const float* __restrict__ w1,
    const float* __restrict__ b1, const float* __restrict__ w2,
    const float* __restrict__ b2, const float* __restrict__ ebias) {
  extern __shared__ float sm[];
  uint32_t* smu = reinterpret_cast<uint32_t*>(sm);
  __shared__ float b1s[C1C], b2s[C2C];

  int tid = threadIdx.x;
  int wid = tid >> 5, lane = tid & 31;
  int gid = lane >> 2, tig = lane & 3;
  int e = blockIdx.x & 7;
  int b = blockIdx.x >> 3;

  // ---- stage weights once (natural layout == B matrix) ----
  const float* w1e = w1 + (size_t)e * C1C * 192;
  for (int i = tid; i < C1C * 192; i += 256) {
    int c1 = i / 192, q = i - c1 * 192;
    smu[W1_OFF + c1 * 196 + q] = f2tf32(w1e[i]);
  }
  const float* w2e = w2 + (size_t)e * C2C * 192;
  for (int i = tid; i < C2C * 192; i += 256) {
    int c2 = i / 192, q = i - c2 * 192;
    smu[W2_OFF + c2 * 196 + q] = f2tf32(w2e[i]);
  }
  if (tid < C1C) b1s[tid] = b1[e * C1C + tid];
  if (tid < C2C) b2s[tid] = b2[e * C2C + tid];
  // zero h1t rows 208..211 (halo read by discarded conv2 rows)
  for (int i = tid; i < 4 * H1_STR; i += 256) smu[H1_OFF + 208 * H1_STR + i] = 0;

  const float* xb = x + (size_t)b * FF * LL;
  const float* ebp = ebias + (size_t)e * UU;
  float* eo = g_expert_out + ((size_t)(e * BB + b)) * UU;

  int mt0 = wid, mt1 = wid + 8;
  bool has2 = (mt1 <= 12);   // 13 m-tiles total

  for (int chunk = 0; chunk < 2; chunk++) {
    int l0 = chunk * 200;
    __syncthreads();  // prior chunk's h2s/store readers done (also covers weights on chunk 0)

    // ---- stage x slab: xs[f][j], j=0..209 <-> xl = l0-6+j (tf32) ----
    for (int i = tid; i < FF * 210; i += 256) {
      int f = i / 210, j = i - f * 210;
      int xl = l0 - 6 + j;
      float v = (xl >= 0 && xl < LL) ? xb[f * LL + xl] : 0.f;
      smu[XS_OFF + f * XS_STR + j] = f2tf32(v);
    }
    __syncthreads();

    // ---- conv1 MMA ----
    float C1[2][8][4];
#pragma unroll
    for (int mi = 0; mi < 2; mi++)
#pragma unroll
      for (int nt = 0; nt < 8; nt++)
#pragma unroll
        for (int j = 0; j < 4; j++) C1[mi][nt][j] = 0.f;

#pragma unroll
    for (int kt = 0; kt < 24; kt++) {
      int q0 = kt * 8 + tig, q1 = q0 + 4;
      uint32_t bf0[8], bf1[8];
#pragma unroll
      for (int nt = 0; nt < 8; nt++) {
        int n = nt * 8 + gid;
        bf0[nt] = smu[W1_OFF + n * 196 + q0];
        bf1[nt] = smu[W1_OFF + n * 196 + q1];
      }
      int f0 = q0 / 3, k0 = q0 - f0 * 3;
      int f1 = q1 / 3, k1 = q1 - f1 * 3;
      int co0 = XS_OFF + f0 * XS_STR + k0;
      int co1 = XS_OFF + f1 * XS_STR + k1;
#pragma unroll
      for (int mi = 0; mi < 2; mi++) {
        if (mi == 0 || has2) {
          int r0 = (mi ? mt1 : mt0) * 16 + gid;
          uint32_t a0 = smu[co0 + r0], a1 = smu[co0 + r0 + 8];
          uint32_t a2 = smu[co1 + r0], a3 = smu[co1 + r0 + 8];
#pragma unroll
          for (int nt = 0; nt < 8; nt++)
            mma_tf32(C1[mi][nt], a0, a1, a2, a3, bf0[nt], bf1[nt]);
        }
      }
    }

    // ---- epilogue 1: h1t[r][c1] = tf32(relu(D1 + b1)), causal mask ----
#pragma unroll
    for (int mi = 0; mi < 2; mi++) {
      if (mi == 0 || has2) {
        int mt = mi ? mt1 : mt0;
        int rA = mt * 16 + gid, rB = rA + 8;
        bool mA = (chunk > 0) || (rA >= 4);  // l1 = l0-4+r >= 0
#pragma unroll
        for (int nt = 0; nt < 8; nt++) {
          int cA = nt * 8 + 2 * tig;
          float v0 = fmaxf(C1[mi][nt][0] + b1s[cA], 0.f);
          float v1 = fmaxf(C1[mi][nt][1] + b1s[cA + 1], 0.f);
          float v2 = fmaxf(C1[mi][nt][2] + b1s[cA], 0.f);
          float v3 = fmaxf(C1[mi][nt][3] + b1s[cA + 1], 0.f);
          if (!mA) { v0 = 0.f; v1 = 0.f; }
          *reinterpret_cast<uint2*>(&smu[H1_OFF + rA * H1_STR + cA]) =
              make_uint2(f2tf32(v0), f2tf32(v1));
          *reinterpret_cast<uint2*>(&smu[H1_OFF + rB * H1_STR + cA]) =
              make_uint2(f2tf32(v2), f2tf32(v3));
        }
      }
    }
    __syncthreads();

    // ---- conv2 MMA ----
    float C2[2][2][4];
#pragma unroll
    for (int mi = 0; mi < 2; mi++)
#pragma unroll
      for (int nt = 0; nt < 2; nt++)
#pragma unroll
        for (int j = 0; j < 4; j++) C2[mi][nt][j] = 0.f;

#pragma unroll
    for (int kt = 0; kt < 24; kt++) {
      int q0 = kt * 8 + tig, q1 = q0 + 4;
      int c10 = q0 / 3, k0 = q0 - c10 * 3;
      int c11 = q1 / 3, k1 = q1 - c11 * 3;
      uint32_t bf0[2], bf1[2];
#pragma unroll
      for (int nt = 0; nt < 2; nt++) {
        int n = nt * 8 + gid;
        bf0[nt] = smu[W2_OFF + n * 196 + q0];
        bf1[nt] = smu[W2_OFF + n * 196 + q1];
      }
#pragma unroll
      for (int mi = 0; mi < 2; mi++) {
        if (mi == 0 || has2) {
          int r0 = (mi ? mt1 : mt0) * 16 + gid;
          uint32_t a0 = smu[H1_OFF + (r0 + 2 * k0) * H1_STR + c10];
          uint32_t a1 = smu[H1_OFF + (r0 + 8 + 2 * k0) * H1_STR + c10];
          uint32_t a2 = smu[H1_OFF + (r0 + 2 * k1) * H1_STR + c11];
          uint32_t a3 = smu[H1_OFF + (r0 + 8 + 2 * k1) * H1_STR + c11];
#pragma unroll
          for (int nt = 0; nt < 2; nt++)
            mma_tf32(C2[mi][nt], a0, a1, a2, a3, bf0[nt], bf1[nt]);
        }
      }
    }

    // ---- epilogue 2: h2s[c2][m2] = relu(D2 + b2)  (overlay xs region) ----
#pragma unroll
    for (int mi = 0; mi < 2; mi++) {
      if (mi == 0 || has2) {
        int mt = mi ? mt1 : mt0;
        int mA = mt * 16 + gid, mB = mA + 8;
#pragma unroll
        for (int nt = 0; nt < 2; nt++) {
          int cA = nt * 8 + 2 * tig;
          float v0 = fmaxf(C2[mi][nt][0] + b2s[cA], 0.f);
          float v1 = fmaxf(C2[mi][nt][1] + b2s[cA + 1], 0.f);
          float v2 = fmaxf(C2[mi][nt][2] + b2s[cA], 0.f);
          float v3 = fmaxf(C2[mi][nt][3] + b2s[cA + 1], 0.f);
          if (mA < 200) {
            sm[XS_OFF + cA * 200 + mA] = v0;
            sm[XS_OFF + (cA + 1) * 200 + mA] = v1;
          }
          if (mB < 200) {
            sm[XS_OFF + cA * 200 + mB] = v2;
            sm[XS_OFF + (cA + 1) * 200 + mB] = v3;
          }
        }
      }
    }
    __syncthreads();

    // ---- store: +expert_bias, relu, coalesced ----
    for (int i = tid; i < C2C * 200; i += 256) {
      int c2 = i / 200, m2 = i - c2 * 200;
      int u = c2 * LL + l0 + m2;
      eo[u] = fmaxf(sm[XS_OFF + i] + ebp[u], 0.f);
    }
  }
}

// ---------------------------------------------------------------------------
// Gates: block = (8 batches, seg of 6400 f). Warp = (t, f-half). Lane = f-off.
// Thread accumulates 8 batches x 8 experts.
// ---------------------------------------------------------------------------
__global__ void __launch_bounds__(256) gates_kernel(
    const float* __restrict__ x, const float* __restrict__ gk) {
  __shared__ float xs[8][1288];
  __shared__ float part[8][64];
  int tid = threadIdx.x;
  int b0 = blockIdx.x * 8, seg = blockIdx.y;
  int w = tid >> 5, lane = tid & 31;
  int t = w >> 1, half = w & 1;

  float acc[8][8];
#pragma unroll
  for (int bi = 0; bi < 8; bi++)
#pragma unroll
    for (int e2 = 0; e2 < 8; e2++) acc[bi][e2] = 0.f;

  for (int c = 0; c < 5; c++) {
    __syncthreads();
    for (int i = tid; i < 8 * 1280; i += 256) {
      int bi = i / 1280, j = i - bi * 1280;
      xs[bi][j] = x[(size_t)(b0 + bi) * FL + seg * 6400 + c * 1280 + j];
    }
    __syncthreads();
    const float4* gp = reinterpret_cast<const float4*>(
        gk + ((size_t)t * FL + seg * 6400 + c * 1280) * EE);
    int fb = half * 640;
#pragma unroll 2
    for (int ii = 0; ii < 20; ii++) {
      int f = fb + ii * 32 + lane;
      float4 ga = gp[2 * f];
      float4 gb2 = gp[2 * f + 1];
#pragma unroll
      for (int bi = 0; bi < 8; bi++) {
        float xv = xs[bi][f];
        acc[bi][0] += xv * ga.x;  acc[bi][1] += xv * ga.y;
        acc[bi][2] += xv * ga.z;  acc[bi][3] += xv * ga.w;
        acc[bi][4] += xv * gb2.x; acc[bi][5] += xv * gb2.y;
        acc[bi][6] += xv * gb2.z; acc[bi][7] += xv * gb2.w;
      }
    }
  }
  // warp reduce over 32 lanes (f)
#pragma unroll
  for (int bi = 0; bi < 8; bi++)
#pragma unroll
    for (int e2 = 0; e2 < 8; e2++) {
      float v = acc[bi][e2];
      v += __shfl_xor_sync(0xffffffffu, v, 16);
      v += __shfl_xor_sync(0xffffffffu, v, 8);
      v += __shfl_xor_sync(0xffffffffu, v, 4);
      v += __shfl_xor_sync(0xffffffffu, v, 2);
      v += __shfl_xor_sync(0xffffffffu, v, 1);
      acc[bi][e2] = v;
    }
  if (lane == 0) {
#pragma unroll
    for (int bi = 0; bi < 8; bi++)
#pragma unroll
      for (int e2 = 0; e2 < 8; e2++) part[w][bi * 8 + e2] = acc[bi][e2];
  }
  __syncthreads();
  {
    int t2 = tid >> 6, rem = tid & 63;
    int bi = rem >> 3, e2 = rem & 7;
    float s = part[t2 * 2][rem] + part[t2 * 2 + 1][rem];
    g_part[(((size_t)seg * TT + t2) * BB + b0 + bi) * EE + e2] = s;
  }
}

// ---------------------------------------------------------------------------
__global__ void __launch_bounds__(256) finalize_gates(
    const float* __restrict__ gbias) {
  int gid = blockIdx.x * 256 + threadIdx.x;
  if (gid >= TT * BB) return;
  int t = gid >> 9, b = gid & 511;
  float v[8];
  float mx = -1e30f;
#pragma unroll
  for (int e = 0; e < 8; e++) {
    float s = gbias[t * 8 + e];
#pragma unroll
    for (int sg = 0; sg < 4; sg++)
      s += g_part[(((size_t)sg * TT + t) * BB + b) * EE + e];
    v[e] = s;
    mx = fmaxf(mx, s);
  }
  float sum = 0.f;
#pragma unroll
  for (int e = 0; e < 8; e++) { v[e] = expf(v[e] - mx); sum += v[e]; }
  float inv = 1.f / sum;
#pragma unroll
  for (int e = 0; e < 8; e++)
    g_gates[((size_t)t * BB + b) * EE + e] = v[e] * inv;
}

// ---------------------------------------------------------------------------
__global__ void __launch_bounds__(256) mix_kernel(
    const float* __restrict__ tbias, float* __restrict__ out) {
  __shared__ float gsh[TT * EE];
  int b = blockIdx.x;
  int tid = threadIdx.x;
  if (tid < TT * EE)
    gsh[tid] = g_gates[((size_t)(tid >> 3) * BB + b) * EE + (tid & 7)];
  __syncthreads();
  int u4 = (blockIdx.y * 256 + tid) * 4;
  if (u4 >= UU) return;

  float4 a[TT];
#pragma unroll
  for (int t = 0; t < TT; t++) {
    float tb = tbias[t];
    a[t] = make_float4(tb, tb, tb, tb);
  }
#pragma unroll
  for (int e = 0; e < EE; e++) {
    float4 v = *reinterpret_cast<const float4*>(
        g_expert_out + ((size_t)(e * BB + b)) * UU + u4);
#pragma unroll
    for (int t = 0; t < TT; t++) {
      float g = gsh[t * 8 + e];
      a[t].x += g * v.x;
      a[t].y += g * v.y;
      a[t].z += g * v.z;
      a[t].w += g * v.w;
    }
  }
#pragma unroll
  for (int t = 0; t < TT; t++)
    *reinterpret_cast<float4*>(out + ((size_t)(t * BB + b)) * UU + u4) = a[t];
}

// ---------------------------------------------------------------------------
extern "C" void kernel_launch(void* const* d_in, const int* in_sizes, int n_in,
                              void* d_out, int out_size) {
  const float* x  = (const float*)d_in[0];
  const float* w1 = (const float*)d_in[1];
  const float* b1 = (const float*)d_in[2];
  const float* w2 = (const float*)d_in[3];
  const float* b2 = (const float*)d_in[4];
  const float* eb = (const float*)d_in[5];
  const float* gk = (const float*)d_in[6];
  const float* gb = (const float*)d_in[7];
  const float* tb = (const float*)d_in[8];
  float* out = (float*)d_out;

  cudaFuncSetAttribute(expert_mma_kernel,
                       cudaFuncAttributeMaxDynamicSharedMemorySize, SMEM_BYTES);

  expert_mma_kernel<<<EE * BB, 256, SMEM_BYTES>>>(x, w1, b1, w2, b2, eb);
  gates_kernel<<<dim3(BB / 8, 4), 256>>>(x, gk);
  finalize_gates<<<8, 256>>>(gb);
  mix_kernel<<<dim3(BB, 7), 256>>>(tb, out);
}

// round 8
// speedup vs baseline: 5.8108x; 1.5247x over previous
#include <cuda_runtime.h>
#include <cuda_fp16.h>
#include <cstdint>

#define BB 512
#define FF 64
#define LL 400
#define EE 8
#define TT 4
#define C1C 64
#define C2C 16
#define UU 6400
#define FL 25600

// scratch
__device__ float g_expert_out[(size_t)EE * BB * UU];   // ~104.9 MB
__device__ float g_gates[TT * BB * EE];
__device__ float g_part[4 * TT * BB * EE];

// ---------- helpers ----------
__device__ __forceinline__ uint32_t pack_h2(float a, float b) {
  __half2 h = __floats2half2_rn(a, b);
  return *reinterpret_cast<uint32_t*>(&h);
}
__device__ __forceinline__ void mma_f16(float* c, uint32_t a0, uint32_t a1,
                                        uint32_t a2, uint32_t a3, uint32_t b0,
                                        uint32_t b1) {
  asm volatile(
      "mma.sync.aligned.m16n8k16.row.col.f32.f16.f16.f32 "
      "{%0,%1,%2,%3}, {%4,%5,%6,%7}, {%8,%9}, {%0,%1,%2,%3};"
      : "+f"(c[0]), "+f"(c[1]), "+f"(c[2]), "+f"(c[3])
      : "r"(a0), "r"(a1), "r"(a2), "r"(a3), "r"(b0), "r"(b1));
}

// smem word layout
// A  : [208 rows][100 h2]  (A1: q=k*64+f pairs; later overwritten as A2: q=k*64+c1)
// W1p: [64][100 h2], W2p: [16][100 h2], h2s: [16][200] f32
#define A_OFF 0
#define A_STR 100
#define W1_OFF 20800
#define W2_OFF 27200
#define H2S_OFF 28800
#define SMEM_WORDS 32000
#define SMEM_BYTES (SMEM_WORDS * 4)   // 128000

// ---------------------------------------------------------------------------
// Expert kernel: fp16 m16n8k16 MMA, f32 accum. Block = (e, b); 2 chunks M=208.
// conv1: D1[208,64] = A1[208,192] x W1[64,192], A1[r][k*64+f] = x[f][l0-6+r+k]
// conv2: D2[208,16] = A2[208,192] x W2[16,192], A2[m][k*64+c1] = h1[m+2k][c1]
//        (row m -> output l = l0 + m, for m < 200)
// ---------------------------------------------------------------------------
__global__ void __launch_bounds__(256, 1) expert_mma_kernel(
    const float* __restrict__ x, const float* __restrict__ w1,
    const float* __restrict__ b1, const float* __restrict__ w2,
    const float* __restrict__ b2, const float* __restrict__ ebias) {
  extern __shared__ float sm[];
  uint32_t* smu = reinterpret_cast<uint32_t*>(sm);
  __shared__ float b1s[C1C], b2s[C2C];

  int tid = threadIdx.x;
  int wid = tid >> 5, lane = tid & 31;
  int gid = lane >> 2, tig = lane & 3;
  int e = blockIdx.x & 7;
  int b = blockIdx.x >> 3;

  // ---- stage packed weights once ----
  const float* w1e = w1 + (size_t)e * C1C * 192;
  for (int i = tid; i < C1C * 96; i += 256) {
    int n = i / 96, qp = i - n * 96;
    int k = qp >> 5, fp = qp & 31;
    smu[W1_OFF + n * A_STR + qp] =
        pack_h2(w1e[n * 192 + 6 * fp + k], w1e[n * 192 + 6 * fp + 3 + k]);
  }
  const float* w2e = w2 + (size_t)e * C2C * 192;
  for (int i = tid; i < C2C * 96; i += 256) {
    int n = i / 96, qp = i - n * 96;
    int k = qp >> 5, cp = qp & 31;
    smu[W2_OFF + n * A_STR + qp] =
        pack_h2(w2e[n * 192 + 6 * cp + k], w2e[n * 192 + 6 * cp + 3 + k]);
  }
  if (tid < C1C) b1s[tid] = b1[e * C1C + tid];
  if (tid < C2C) b2s[tid] = b2[e * C2C + tid];

  const float* xb = x + (size_t)b * FF * LL;
  const float* ebp = ebias + (size_t)e * UU;
  float* eo = g_expert_out + ((size_t)(e * BB + b)) * UU;

  int mt0 = wid, mt1 = wid + 8;
  bool has2 = (mt1 <= 12);   // 13 m-tiles

  for (int chunk = 0; chunk < 2; chunk++) {
    int l0 = chunk * 200;
    __syncthreads();  // prior chunk's h2s readers / A readers done

    // ---- stage A1: pairs (f=2fp, 2fp+1), 3 shifted copies over k ----
    for (int i = tid; i < 32 * 210; i += 256) {
      int fp = i / 210, j = i - fp * 210;
      int gl = l0 - 6 + j;
      float v0 = 0.f, v1 = 0.f;
      if (gl >= 0 && gl < LL) {
        v0 = xb[(2 * fp) * LL + gl];
        v1 = xb[(2 * fp + 1) * LL + gl];
      }
      uint32_t pk = pack_h2(v0, v1);
#pragma unroll
      for (int k = 0; k < 3; k++) {
        int r = j - k;
        if (r >= 0 && r < 208) smu[A_OFF + r * A_STR + k * 32 + fp] = pk;
      }
    }
    __syncthreads();

    // ---- conv1 MMA: 12 k-steps of k16 ----
    float C1[2][8][4];
#pragma unroll
    for (int mi = 0; mi < 2; mi++)
#pragma unroll
      for (int nt = 0; nt < 8; nt++)
#pragma unroll
        for (int j = 0; j < 4; j++) C1[mi][nt][j] = 0.f;

#pragma unroll
    for (int kt = 0; kt < 12; kt++) {
      int q0 = kt * 8 + tig;
      uint32_t bf0[8], bf1[8];
#pragma unroll
      for (int nt = 0; nt < 8; nt++) {
        int n = nt * 8 + gid;
        bf0[nt] = smu[W1_OFF + n * A_STR + q0];
        bf1[nt] = smu[W1_OFF + n * A_STR + q0 + 4];
      }
#pragma unroll
      for (int mi = 0; mi < 2; mi++) {
        if (mi == 0 || has2) {
          int r0 = (mi ? mt1 : mt0) * 16 + gid;
          uint32_t a0 = smu[A_OFF + r0 * A_STR + q0];
          uint32_t a1 = smu[A_OFF + (r0 + 8) * A_STR + q0];
          uint32_t a2 = smu[A_OFF + r0 * A_STR + q0 + 4];
          uint32_t a3 = smu[A_OFF + (r0 + 8) * A_STR + q0 + 4];
#pragma unroll
          for (int nt = 0; nt < 8; nt++)
            mma_f16(C1[mi][nt], a0, a1, a2, a3, bf0[nt], bf1[nt]);
        }
      }
    }
    __syncthreads();  // all conv1 A reads done before epi1 overwrites A

    // ---- epilogue 1: A2[m][k*32+cp] = h2(relu(D1+b1)) at m = r-2k ----
#pragma unroll
    for (int mi = 0; mi < 2; mi++) {
      if (mi == 0 || has2) {
        int mt = mi ? mt1 : mt0;
        int rA = mt * 16 + gid, rB = rA + 8;
        bool mA = (chunk > 0) || (rA >= 4);  // causal: l1 = l0-4+r >= 0
#pragma unroll
        for (int nt = 0; nt < 8; nt++) {
          int cA = nt * 8 + 2 * tig;
          float v0 = fmaxf(C1[mi][nt][0] + b1s[cA], 0.f);
          float v1 = fmaxf(C1[mi][nt][1] + b1s[cA + 1], 0.f);
          float v2 = fmaxf(C1[mi][nt][2] + b1s[cA], 0.f);
          float v3 = fmaxf(C1[mi][nt][3] + b1s[cA + 1], 0.f);
          if (!mA) { v0 = 0.f; v1 = 0.f; }
          uint32_t pkA = pack_h2(v0, v1);
          uint32_t pkB = pack_h2(v2, v3);
          int cp = nt * 4 + tig;
#pragma unroll
          for (int k = 0; k < 3; k++) {
            int m = rA - 2 * k;
            if (m >= 0) smu[A_OFF + m * A_STR + k * 32 + cp] = pkA;
            smu[A_OFF + (rB - 2 * k) * A_STR + k * 32 + cp] = pkB;
          }
        }
      }
    }
    __syncthreads();

    // ---- conv2 MMA ----
    float C2[2][2][4];
#pragma unroll
    for (int mi = 0; mi < 2; mi++)
#pragma unroll
      for (int nt = 0; nt < 2; nt++)
#pragma unroll
        for (int j = 0; j < 4; j++) C2[mi][nt][j] = 0.f;

#pragma unroll
    for (int kt = 0; kt < 12; kt++) {
      int q0 = kt * 8 + tig;
      uint32_t bf0[2], bf1[2];
#pragma unroll
      for (int nt = 0; nt < 2; nt++) {
        int n = nt * 8 + gid;
        bf0[nt] = smu[W2_OFF + n * A_STR + q0];
        bf1[nt] = smu[W2_OFF + n * A_STR + q0 + 4];
      }
#pragma unroll
      for (int mi = 0; mi < 2; mi++) {
        if (mi == 0 || has2) {
          int r0 = (mi ? mt1 : mt0) * 16 + gid;
          uint32_t a0 = smu[A_OFF + r0 * A_STR + q0];
          uint32_t a1 = smu[A_OFF + (r0 + 8) * A_STR + q0];
          uint32_t a2 = smu[A_OFF + r0 * A_STR + q0 + 4];
          uint32_t a3 = smu[A_OFF + (r0 + 8) * A_STR + q0 + 4];
#pragma unroll
          for (int nt = 0; nt < 2; nt++)
            mma_f16(C2[mi][nt], a0, a1, a2, a3, bf0[nt], bf1[nt]);
        }
      }
    }

    // ---- epilogue 2: h2s[c2][m] = relu(D2 + b2) ----
#pragma unroll
    for (int mi = 0; mi < 2; mi++) {
      if (mi == 0 || has2) {
        int mt = mi ? mt1 : mt0;
        int mA = mt * 16 + gid, mB = mA + 8;
#pragma unroll
        for (int nt = 0; nt < 2; nt++) {
          int cA = nt * 8 + 2 * tig;
          float v0 = fmaxf(C2[mi][nt][0] + b2s[cA], 0.f);
          float v1 = fmaxf(C2[mi][nt][1] + b2s[cA + 1], 0.f);
          float v2 = fmaxf(C2[mi][nt][2] + b2s[cA], 0.f);
          float v3 = fmaxf(C2[mi][nt][3] + b2s[cA + 1], 0.f);
          if (mA < 200) {
            sm[H2S_OFF + cA * 200 + mA] = v0;
            sm[H2S_OFF + (cA + 1) * 200 + mA] = v1;
          }
          if (mB < 200) {
            sm[H2S_OFF + cA * 200 + mB] = v2;
            sm[H2S_OFF + (cA + 1) * 200 + mB] = v3;
          }
        }
      }
    }
    __syncthreads();

    // ---- store: +expert_bias, relu, coalesced ----
    for (int i = tid; i < C2C * 200; i += 256) {
      int c2 = i / 200, m = i - c2 * 200;
      int u = c2 * LL + l0 + m;
      eo[u] = fmaxf(sm[H2S_OFF + i] + ebp[u], 0.f);
    }
  }
}

// ---------------------------------------------------------------------------
// Gates (unchanged): block = (8 batches, seg of 6400). Warp = (t, f-half).
// ---------------------------------------------------------------------------
__global__ void __launch_bounds__(256) gates_kernel(
    const float* __restrict__ x, const float* __restrict__ gk) {
  __shared__ float xs[8][1288];
  __shared__ float part[8][64];
  int tid = threadIdx.x;
  int b0 = blockIdx.x * 8, seg = blockIdx.y;
  int w = tid >> 5, lane = tid & 31;
  int t = w >> 1, half = w & 1;

  float acc[8][8];
#pragma unroll
  for (int bi = 0; bi < 8; bi++)
#pragma unroll
    for (int e2 = 0; e2 < 8; e2++) acc[bi][e2] = 0.f;

  for (int c = 0; c < 5; c++) {
    __syncthreads();
    for (int i = tid; i < 8 * 1280; i += 256) {
      int bi = i / 1280, j = i - bi * 1280;
      xs[bi][j] = x[(size_t)(b0 + bi) * FL + seg * 6400 + c * 1280 + j];
    }
    __syncthreads();
    const float4* gp = reinterpret_cast<const float4*>(
        gk + ((size_t)t * FL + seg * 6400 + c * 1280) * EE);
    int fb = half * 640;
#pragma unroll 2
    for (int ii = 0; ii < 20; ii++) {
      int f = fb + ii * 32 + lane;
      float4 ga = gp[2 * f];
      float4 gb2 = gp[2 * f + 1];
#pragma unroll
      for (int bi = 0; bi < 8; bi++) {
        float xv = xs[bi][f];
        acc[bi][0] += xv * ga.x;  acc[bi][1] += xv * ga.y;
        acc[bi][2] += xv * ga.z;  acc[bi][3] += xv * ga.w;
        acc[bi][4] += xv * gb2.x; acc[bi][5] += xv * gb2.y;
        acc[bi][6] += xv * gb2.z; acc[bi][7] += xv * gb2.w;
      }
    }
  }
#pragma unroll
  for (int bi = 0; bi < 8; bi++)
#pragma unroll
    for (int e2 = 0; e2 < 8; e2++) {
      float v = acc[bi][e2];
      v += __shfl_xor_sync(0xffffffffu, v, 16);
      v += __shfl_xor_sync(0xffffffffu, v, 8);
      v += __shfl_xor_sync(0xffffffffu, v, 4);
      v += __shfl_xor_sync(0xffffffffu, v, 2);
      v += __shfl_xor_sync(0xffffffffu, v, 1);
      acc[bi][e2] = v;
    }
  if (lane == 0) {
#pragma unroll
    for (int bi = 0; bi < 8; bi++)
#pragma unroll
      for (int e2 = 0; e2 < 8; e2++) part[w][bi * 8 + e2] = acc[bi][e2];
  }
  __syncthreads();
  {
    int t2 = tid >> 6, rem = tid & 63;
    int bi = rem >> 3, e2 = rem & 7;
    float s = part[t2 * 2][rem] + part[t2 * 2 + 1][rem];
    g_part[(((size_t)seg * TT + t2) * BB + b0 + bi) * EE + e2] = s;
  }
}

// ---------------------------------------------------------------------------
__global__ void __launch_bounds__(256) finalize_gates(
    const float* __restrict__ gbias) {
  int gid = blockIdx.x * 256 + threadIdx.x;
  if (gid >= TT * BB) return;
  int t = gid >> 9, b = gid & 511;
  float v[8];
  float mx = -1e30f;
#pragma unroll
  for (int e = 0; e < 8; e++) {
    float s = gbias[t * 8 + e];
#pragma unroll
    for (int sg = 0; sg < 4; sg++)
      s += g_part[(((size_t)sg * TT + t) * BB + b) * EE + e];
    v[e] = s;
    mx = fmaxf(mx, s);
  }
  float sum = 0.f;
#pragma unroll
  for (int e = 0; e < 8; e++) { v[e] = expf(v[e] - mx); sum += v[e]; }
  float inv = 1.f / sum;
#pragma unroll
  for (int e = 0; e < 8; e++)
    g_gates[((size_t)t * BB + b) * EE + e] = v[e] * inv;
}

// ---------------------------------------------------------------------------
__global__ void __launch_bounds__(256) mix_kernel(
    const float* __restrict__ tbias, float* __restrict__ out) {
  __shared__ float gsh[TT * EE];
  int b = blockIdx.x;
  int tid = threadIdx.x;
  if (tid < TT * EE)
    gsh[tid] = g_gates[((size_t)(tid >> 3) * BB + b) * EE + (tid & 7)];
  __syncthreads();
  int u4 = (blockIdx.y * 256 + tid) * 4;
  if (u4 >= UU) return;

  float4 a[TT];
#pragma unroll
  for (int t = 0; t < TT; t++) {
    float tb = tbias[t];
    a[t] = make_float4(tb, tb, tb, tb);
  }
#pragma unroll
  for (int e = 0; e < EE; e++) {
    float4 v = *reinterpret_cast<const float4*>(
        g_expert_out + ((size_t)(e * BB + b)) * UU + u4);
#pragma unroll
    for (int t = 0; t < TT; t++) {
      float g = gsh[t * 8 + e];
      a[t].x += g * v.x;
      a[t].y += g * v.y;
      a[t].z += g * v.z;
      a[t].w += g * v.w;
    }
  }
#pragma unroll
  for (int t = 0; t < TT; t++)
    *reinterpret_cast<float4*>(out + ((size_t)(t * BB + b)) * UU + u4) = a[t];
}

// ---------------------------------------------------------------------------
extern "C" void kernel_launch(void* const* d_in, const int* in_sizes, int n_in,
                              void* d_out, int out_size) {
  const float* x  = (const float*)d_in[0];
  const float* w1 = (const float*)d_in[1];
  const float* b1 = (const float*)d_in[2];
  const float* w2 = (const float*)d_in[3];
  const float* b2 = (const float*)d_in[4];
  const float* eb = (const float*)d_in[5];
  const float* gk = (const float*)d_in[6];
  const float* gb = (const float*)d_in[7];
  const float* tb = (const float*)d_in[8];
  float* out = (float*)d_out;

  cudaFuncSetAttribute(expert_mma_kernel,
                       cudaFuncAttributeMaxDynamicSharedMemorySize, SMEM_BYTES);

  expert_mma_kernel<<<EE * BB, 256, SMEM_BYTES>>>(x, w1, b1, w2, b2, eb);
  gates_kernel<<<dim3(BB / 8, 4), 256>>>(x, gk);
  finalize_gates<<<8, 256>>>(gb);
  mix_kernel<<<dim3(BB, 7), 256>>>(tb, out);
}

// round 9
// speedup vs baseline: 7.7200x; 1.3286x over previous
#include <cuda_runtime.h>
#include <cuda_fp16.h>
#include <cstdint>

#define BB 512
#define FF 64
#define LL 400
#define EE 8
#define TT 4
#define C1C 64
#define C2C 16
#define UU 6400
#define FL 25600

// scratch
__device__ float g_expert_out[(size_t)EE * BB * UU];   // ~104.9 MB
__device__ float g_gates[TT * BB * EE];
__device__ float g_part[4 * TT * BB * EE];

// ---------- helpers ----------
__device__ __forceinline__ uint32_t pack_h2(float a, float b) {
  __half2 h = __floats2half2_rn(a, b);
  return *reinterpret_cast<uint32_t*>(&h);
}
__device__ __forceinline__ void mma_f16(float* c, uint32_t a0, uint32_t a1,
                                        uint32_t a2, uint32_t a3, uint32_t b0,
                                        uint32_t b1) {
  asm volatile(
      "mma.sync.aligned.m16n8k16.row.col.f32.f16.f16.f32 "
      "{%0,%1,%2,%3}, {%4,%5,%6,%7}, {%8,%9}, {%0,%1,%2,%3};"
      : "+f"(c[0]), "+f"(c[1]), "+f"(c[2]), "+f"(c[3])
      : "r"(a0), "r"(a1), "r"(a2), "r"(a3), "r"(b0), "r"(b1));
}
__device__ __forceinline__ void ldsm4(uint32_t& a0, uint32_t& a1, uint32_t& a2,
                                      uint32_t& a3, uint32_t addr) {
  asm volatile("ldmatrix.sync.aligned.m8n8.x4.shared.b16 {%0,%1,%2,%3}, [%4];"
               : "=r"(a0), "=r"(a1), "=r"(a2), "=r"(a3) : "r"(addr));
}
__device__ __forceinline__ void ldsm2(uint32_t& b0, uint32_t& b1,
                                      uint32_t addr) {
  asm volatile("ldmatrix.sync.aligned.m8n8.x2.shared.b16 {%0,%1}, [%2];"
               : "=r"(b0), "=r"(b1) : "r"(addr));
}

// smem word layout. A: [112 rows][100 h2-words] (A1 then rebuilt as A2).
// W1p: [64][100], W2p: [16][100], h2s: [16][100] f32.
#define A_STR 100
#define A_OFF 0
#define W1_OFF 11200
#define W2_OFF 17600
#define H2S_OFF 19200
#define SMEM_WORDS 20864
#define SMEM_BYTES (SMEM_WORDS * 4)   // 83456 -> 2 CTAs/SM

// ---------------------------------------------------------------------------
// Expert kernel: fp16 m16n8k16, ldmatrix operands. Block=(e,b); 4 chunks M=112.
// chunk c: output l = l0+m (m<100), l0 = 100c.
// conv1: D1[112,64] = A1[112,192] x W1[64,192], A1[r][k*64+f]=x[f][l0-6+r+k]
//        h1 row r <-> l1 = l0-4+r  (rows 0..103 valid)
// conv2: D2[112,16] = A2[112,192] x W2[16,192], A2[m][k*64+c1]=h1[m+2k][c1]
// ---------------------------------------------------------------------------
__global__ void __launch_bounds__(256, 2) expert_mma_kernel(
    const float* __restrict__ x, const float* __restrict__ w1,
    const float* __restrict__ b1, const float* __restrict__ w2,
    const float* __restrict__ b2, const float* __restrict__ ebias) {
  extern __shared__ float sm[];
  uint32_t* smu = reinterpret_cast<uint32_t*>(sm);
  __shared__ float b1s[C1C], b2s[C2C];

  int tid = threadIdx.x;
  int wid = tid >> 5, lane = tid & 31;
  int gid = lane >> 2, tig = lane & 3;
  int l15 = lane & 15;
  int e = blockIdx.x & 7;
  int b = blockIdx.x >> 3;
  uint32_t smb = (uint32_t)__cvta_generic_to_shared(sm);

  // ---- stage packed weights once ----
  const float* w1e = w1 + (size_t)e * C1C * 192;
  for (int i = tid; i < C1C * 96; i += 256) {
    int n = i / 96, qp = i - n * 96;
    int k = qp >> 5, fp = qp & 31;
    smu[W1_OFF + n * A_STR + qp] =
        pack_h2(w1e[n * 192 + 6 * fp + k], w1e[n * 192 + 6 * fp + 3 + k]);
  }
  const float* w2e = w2 + (size_t)e * C2C * 192;
  for (int i = tid; i < C2C * 96; i += 256) {
    int n = i / 96, qp = i - n * 96;
    int k = qp >> 5, cp = qp & 31;
    smu[W2_OFF + n * A_STR + qp] =
        pack_h2(w2e[n * 192 + 6 * cp + k], w2e[n * 192 + 6 * cp + 3 + k]);
  }
  if (tid < C1C) b1s[tid] = b1[e * C1C + tid];
  if (tid < C2C) b2s[tid] = b2[e * C2C + tid];

  const float* xb = x + (size_t)b * FF * LL;
  const float* ebp = ebias + (size_t)e * UU;
  float* eo = g_expert_out + ((size_t)(e * BB + b)) * UU;

  bool active = (wid < 7);   // 7 m-tiles, warp 7 only helps stage/store
  int R0 = wid * 16;

  // ldmatrix lane address bases (bytes)
  uint32_t aA_base =
      smb + ((A_OFF + (R0 + l15) * A_STR) << 2) + ((lane >> 4) << 4);
  uint32_t bW1_base =
      smb + ((W1_OFF + (l15 & 7) * A_STR) << 2) + ((l15 >> 3) << 4);
  uint32_t bW2_base =
      smb + ((W2_OFF + (l15 & 7) * A_STR) << 2) + ((l15 >> 3) << 4);

  for (int chunk = 0; chunk < 4; chunk++) {
    int l0 = chunk * 100;
    __syncthreads();  // prev chunk's A/h2s readers done

    // ---- stage A1: pairs (2fp, 2fp+1), 3 shifted k-copies ----
    for (int i = tid; i < 32 * 106; i += 256) {
      int fp = i / 106, j = i - fp * 106;
      int gl = l0 - 6 + j;
      float v0 = 0.f, v1 = 0.f;
      if (gl >= 0) {
        v0 = xb[(2 * fp) * LL + gl];
        v1 = xb[(2 * fp + 1) * LL + gl];
      }
      uint32_t pk = pack_h2(v0, v1);
#pragma unroll
      for (int k = 0; k < 3; k++) {
        int r = j - k;
        if (r >= 0 && r < 104) smu[A_OFF + r * A_STR + k * 32 + fp] = pk;
      }
    }
    __syncthreads();

    // ---- conv1 MMA ----
    float C1[8][4];
#pragma unroll
    for (int nt = 0; nt < 8; nt++)
#pragma unroll
      for (int j = 0; j < 4; j++) C1[nt][j] = 0.f;

    if (active) {
#pragma unroll
      for (int kt = 0; kt < 12; kt++) {
        uint32_t a0, a1, a2, a3;
        ldsm4(a0, a1, a2, a3, aA_base + kt * 32);
#pragma unroll
        for (int nt = 0; nt < 8; nt++) {
          uint32_t b0, b1v;
          ldsm2(b0, b1v, bW1_base + nt * 3200 + kt * 32);
          mma_f16(C1[nt], a0, a1, a2, a3, b0, b1v);
        }
      }
    }
    __syncthreads();  // conv1 A reads done before epi1 overwrites A

    // ---- epilogue 1: A2[m][k*32+cp] = h2(relu(D1+b1)) at m = r-2k ----
    if (active) {
      int rA = R0 + gid, rB = rA + 8;
      bool mA = (chunk > 0) || (rA >= 4);  // causal: l1 = l0-4+r >= 0
#pragma unroll
      for (int nt = 0; nt < 8; nt++) {
        int cA = nt * 8 + 2 * tig;
        float v0 = fmaxf(C1[nt][0] + b1s[cA], 0.f);
        float v1 = fmaxf(C1[nt][1] + b1s[cA + 1], 0.f);
        float v2 = fmaxf(C1[nt][2] + b1s[cA], 0.f);
        float v3 = fmaxf(C1[nt][3] + b1s[cA + 1], 0.f);
        if (!mA) { v0 = 0.f; v1 = 0.f; }
        uint32_t pkA = pack_h2(v0, v1);
        uint32_t pkB = pack_h2(v2, v3);
        int cp = nt * 4 + tig;
#pragma unroll
        for (int k = 0; k < 3; k++) {
          int m = rA - 2 * k;
          if (m >= 0) smu[A_OFF + m * A_STR + k * 32 + cp] = pkA;
          smu[A_OFF + (rB - 2 * k) * A_STR + k * 32 + cp] = pkB;
        }
      }
    }
    __syncthreads();

    // ---- conv2 MMA + epilogue 2 ----
    if (active) {
      float C2[2][4];
#pragma unroll
      for (int nt = 0; nt < 2; nt++)
#pragma unroll
        for (int j = 0; j < 4; j++) C2[nt][j] = 0.f;
#pragma unroll
      for (int kt = 0; kt < 12; kt++) {
        uint32_t a0, a1, a2, a3;
        ldsm4(a0, a1, a2, a3, aA_base + kt * 32);
#pragma unroll
        for (int nt = 0; nt < 2; nt++) {
          uint32_t b0, b1v;
          ldsm2(b0, b1v, bW2_base + nt * 3200 + kt * 32);
          mma_f16(C2[nt], a0, a1, a2, a3, b0, b1v);
        }
      }
      int mA = R0 + gid, mB = mA + 8;
#pragma unroll
      for (int nt = 0; nt < 2; nt++) {
        int cA = nt * 8 + 2 * tig;
        float v0 = fmaxf(C2[nt][0] + b2s[cA], 0.f);
        float v1 = fmaxf(C2[nt][1] + b2s[cA + 1], 0.f);
        float v2 = fmaxf(C2[nt][2] + b2s[cA], 0.f);
        float v3 = fmaxf(C2[nt][3] + b2s[cA + 1], 0.f);
        if (mA < 100) {
          sm[H2S_OFF + cA * 100 + mA] = v0;
          sm[H2S_OFF + (cA + 1) * 100 + mA] = v1;
        }
        if (mB < 100) {
          sm[H2S_OFF + cA * 100 + mB] = v2;
          sm[H2S_OFF + (cA + 1) * 100 + mB] = v3;
        }
      }
    }
    __syncthreads();

    // ---- store: +expert_bias, relu, coalesced ----
    for (int i = tid; i < C2C * 100; i += 256) {
      int c2 = i / 100, m = i - c2 * 100;
      int u = c2 * LL + l0 + m;
      eo[u] = fmaxf(sm[H2S_OFF + i] + ebp[u], 0.f);
    }
  }
}

// ---------------------------------------------------------------------------
// Gates: block = (8 batches, seg of 6400). Warp = (t, f-half).
// ---------------------------------------------------------------------------
__global__ void __launch_bounds__(256) gates_kernel(
    const float* __restrict__ x, const float* __restrict__ gk) {
  __shared__ float xs[8][1288];
  __shared__ float part[8][64];
  int tid = threadIdx.x;
  int b0 = blockIdx.x * 8, seg = blockIdx.y;
  int w = tid >> 5, lane = tid & 31;
  int t = w >> 1, half = w & 1;

  float acc[8][8];
#pragma unroll
  for (int bi = 0; bi < 8; bi++)
#pragma unroll
    for (int e2 = 0; e2 < 8; e2++) acc[bi][e2] = 0.f;

  for (int c = 0; c < 5; c++) {
    __syncthreads();
    for (int i = tid; i < 8 * 1280; i += 256) {
      int bi = i / 1280, j = i - bi * 1280;
      xs[bi][j] = x[(size_t)(b0 + bi) * FL + seg * 6400 + c * 1280 + j];
    }
    __syncthreads();
    const float4* gp = reinterpret_cast<const float4*>(
        gk + ((size_t)t * FL + seg * 6400 + c * 1280) * EE);
    int fb = half * 640;
#pragma unroll 2
    for (int ii = 0; ii < 20; ii++) {
      int f = fb + ii * 32 + lane;
      float4 ga = gp[2 * f];
      float4 gb2 = gp[2 * f + 1];
#pragma unroll
      for (int bi = 0; bi < 8; bi++) {
        float xv = xs[bi][f];
        acc[bi][0] += xv * ga.x;  acc[bi][1] += xv * ga.y;
        acc[bi][2] += xv * ga.z;  acc[bi][3] += xv * ga.w;
        acc[bi][4] += xv * gb2.x; acc[bi][5] += xv * gb2.y;
        acc[bi][6] += xv * gb2.z; acc[bi][7] += xv * gb2.w;
      }
    }
  }
#pragma unroll
  for (int bi = 0; bi < 8; bi++)
#pragma unroll
    for (int e2 = 0; e2 < 8; e2++) {
      float v = acc[bi][e2];
      v += __shfl_xor_sync(0xffffffffu, v, 16);
      v += __shfl_xor_sync(0xffffffffu, v, 8);
      v += __shfl_xor_sync(0xffffffffu, v, 4);
      v += __shfl_xor_sync(0xffffffffu, v, 2);
      v += __shfl_xor_sync(0xffffffffu, v, 1);
      acc[bi][e2] = v;
    }
  if (lane == 0) {
#pragma unroll
    for (int bi = 0; bi < 8; bi++)
#pragma unroll
      for (int e2 = 0; e2 < 8; e2++) part[w][bi * 8 + e2] = acc[bi][e2];
  }
  __syncthreads();
  {
    int t2 = tid >> 6, rem = tid & 63;
    int bi = rem >> 3, e2 = rem & 7;
    float s = part[t2 * 2][rem] + part[t2 * 2 + 1][rem];
    g_part[(((size_t)seg * TT + t2) * BB + b0 + bi) * EE + e2] = s;
  }
}

// ---------------------------------------------------------------------------
__global__ void __launch_bounds__(256) finalize_gates(
    const float* __restrict__ gbias) {
  int gid = blockIdx.x * 256 + threadIdx.x;
  if (gid >= TT * BB) return;
  int t = gid >> 9, b = gid & 511;
  float v[8];
  float mx = -1e30f;
#pragma unroll
  for (int e = 0; e < 8; e++) {
    float s = gbias[t * 8 + e];
#pragma unroll
    for (int sg = 0; sg < 4; sg++)
      s += g_part[(((size_t)sg * TT + t) * BB + b) * EE + e];
    v[e] = s;
    mx = fmaxf(mx, s);
  }
  float sum = 0.f;
#pragma unroll
  for (int e = 0; e < 8; e++) { v[e] = expf(v[e] - mx); sum += v[e]; }
  float inv = 1.f / sum;
#pragma unroll
  for (int e = 0; e < 8; e++)
    g_gates[((size_t)t * BB + b) * EE + e] = v[e] * inv;
}

// ---------------------------------------------------------------------------
__global__ void __launch_bounds__(256) mix_kernel(
    const float* __restrict__ tbias, float* __restrict__ out) {
  __shared__ float gsh[TT * EE];
  int b = blockIdx.x;
  int tid = threadIdx.x;
  if (tid < TT * EE)
    gsh[tid] = g_gates[((size_t)(tid >> 3) * BB + b) * EE + (tid & 7)];
  __syncthreads();
  int u4 = (blockIdx.y * 256 + tid) * 4;
  if (u4 >= UU) return;

  float4 a[TT];
#pragma unroll
  for (int t = 0; t < TT; t++) {
    float tb = tbias[t];
    a[t] = make_float4(tb, tb, tb, tb);
  }
#pragma unroll
  for (int e = 0; e < EE; e++) {
    float4 v = *reinterpret_cast<const float4*>(
        g_expert_out + ((size_t)(e * BB + b)) * UU + u4);
#pragma unroll
    for (int t = 0; t < TT; t++) {
      float g = gsh[t * 8 + e];
      a[t].x += g * v.x;
      a[t].y += g * v.y;
      a[t].z += g * v.z;
      a[t].w += g * v.w;
    }
  }
#pragma unroll
  for (int t = 0; t < TT; t++)
    *reinterpret_cast<float4*>(out + ((size_t)(t * BB + b)) * UU + u4) = a[t];
}

// ---------------------------------------------------------------------------
extern "C" void kernel_launch(void* const* d_in, const int* in_sizes, int n_in,
                              void* d_out, int out_size) {
  const float* x  = (const float*)d_in[0];
  const float* w1 = (const float*)d_in[1];
  const float* b1 = (const float*)d_in[2];
  const float* w2 = (const float*)d_in[3];
  const float* b2 = (const float*)d_in[4];
  const float* eb = (const float*)d_in[5];
  const float* gk = (const float*)d_in[6];
  const float* gb = (const float*)d_in[7];
  const float* tb = (const float*)d_in[8];
  float* out = (float*)d_out;

  cudaFuncSetAttribute(expert_mma_kernel,
                       cudaFuncAttributeMaxDynamicSharedMemorySize, SMEM_BYTES);

  expert_mma_kernel<<<EE * BB, 256, SMEM_BYTES>>>(x, w1, b1, w2, b2, eb);
  gates_kernel<<<dim3(BB / 8, 4), 256>>>(x, gk);
  finalize_gates<<<8, 256>>>(gb);
  mix_kernel<<<dim3(BB, 7), 256>>>(tb, out);
}

// round 10
// speedup vs baseline: 9.1034x; 1.1792x over previous
#include <cuda_runtime.h>
#include <cuda_fp16.h>
#include <cstdint>

#define BB 512
#define FF 64
#define LL 400
#define EE 8
#define TT 4
#define C1C 64
#define C2C 16
#define UU 6400
#define FL 25600

// scratch
__device__ float g_expert_out[(size_t)EE * BB * UU];   // ~104.9 MB
__device__ float g_gates[TT * BB * EE];
__device__ float g_part[4 * TT * BB * EE];

// ---------- helpers ----------
__device__ __forceinline__ uint32_t pack_h2(float a, float b) {
  __half2 h = __floats2half2_rn(a, b);
  return *reinterpret_cast<uint32_t*>(&h);
}
__device__ __forceinline__ void mma_f16(float* c, uint32_t a0, uint32_t a1,
                                        uint32_t a2, uint32_t a3, uint32_t b0,
                                        uint32_t b1) {
  asm volatile(
      "mma.sync.aligned.m16n8k16.row.col.f32.f16.f16.f32 "
      "{%0,%1,%2,%3}, {%4,%5,%6,%7}, {%8,%9}, {%0,%1,%2,%3};"
      : "+f"(c[0]), "+f"(c[1]), "+f"(c[2]), "+f"(c[3])
      : "r"(a0), "r"(a1), "r"(a2), "r"(a3), "r"(b0), "r"(b1));
}
__device__ __forceinline__ void ldsm4(uint32_t& a0, uint32_t& a1, uint32_t& a2,
                                      uint32_t& a3, uint32_t addr) {
  asm volatile("ldmatrix.sync.aligned.m8n8.x4.shared.b16 {%0,%1,%2,%3}, [%4];"
               : "=r"(a0), "=r"(a1), "=r"(a2), "=r"(a3) : "r"(addr));
}

// smem word layout.
// A: [116 rows][36 words] — row = l-index; A1 cols = f-pairs, then rebuilt in
//    place as A2 (cols = c1-pairs). Tap shift done via ldmatrix row offset.
// W1p: [64][100], W2p: [16][100]  (word idx = k*32 + fg*8 + w, f = 16fg+2w)
// h2s: [16][100] f32
#define A_STR 36
#define A_OFF 0
#define W1_OFF 4176
#define W2_OFF 10576
#define H2S_OFF 12176
#define SMEM_WORDS 13776
#define SMEM_BYTES (SMEM_WORDS * 4)   // 55104 -> 3 CTAs/SM

// ---------------------------------------------------------------------------
// Expert kernel: fp16 m16n8k16. Block=(e, b-b_base); 4 chunks of M=112.
// conv1: rows r=0..111, h1(l0-4+r) = relu(sum_{f,k} x[f][l0-6+r+k] w1);
//        A read at row r+k (ldmatrix row offset), cols f.
// conv2: rows m=0..99 valid, out(l0+m) = relu(sum_{c1,k} h1[m+2k][c1] w2);
//        A2 read at row m+2k.
// ---------------------------------------------------------------------------
__global__ void __launch_bounds__(256, 3) expert_mma_kernel(
    const float* __restrict__ x, const float* __restrict__ w1,
    const float* __restrict__ b1, const float* __restrict__ w2,
    const float* __restrict__ b2, const float* __restrict__ ebias,
    int b_base) {
  extern __shared__ float sm[];
  uint32_t* smu = reinterpret_cast<uint32_t*>(sm);
  __shared__ float b1s[C1C], b2s[C2C];

  int tid = threadIdx.x;
  int wid = tid >> 5, lane = tid & 31;
  int gid = lane >> 2, tig = lane & 3;
  int l15 = lane & 15;
  int e = blockIdx.x & 7;
  int b = b_base + (blockIdx.x >> 3);
  uint32_t smb = (uint32_t)__cvta_generic_to_shared(sm);

  // ---- stage packed weights once: word idx = k*32 + fg*8 + w ----
  const float* w1e = w1 + (size_t)e * C1C * 192;
  for (int i = tid; i < C1C * 96; i += 256) {
    int n = i / 96, idx = i - n * 96;
    int k = idx >> 5, fg = (idx >> 3) & 3, w = idx & 7;
    int f0 = fg * 16 + 2 * w;
    smu[W1_OFF + n * 100 + idx] =
        pack_h2(w1e[n * 192 + f0 * 3 + k], w1e[n * 192 + (f0 + 1) * 3 + k]);
  }
  const float* w2e = w2 + (size_t)e * C2C * 192;
  for (int i = tid; i < C2C * 96; i += 256) {
    int n = i / 96, idx = i - n * 96;
    int k = idx >> 5, fg = (idx >> 3) & 3, w = idx & 7;
    int c0 = fg * 16 + 2 * w;
    smu[W2_OFF + n * 100 + idx] =
        pack_h2(w2e[n * 192 + c0 * 3 + k], w2e[n * 192 + (c0 + 1) * 3 + k]);
  }
  if (tid < C1C) b1s[tid] = b1[e * C1C + tid];
  if (tid < C2C) b2s[tid] = b2[e * C2C + tid];
  // zero A rows 112..115 (read by discarded conv2 rows, never written)
  for (int i = tid; i < 4 * A_STR; i += 256) smu[A_OFF + 112 * A_STR + i] = 0;

  const float* xb = x + (size_t)b * FF * LL;
  const float* ebp = ebias + (size_t)e * UU;
  float* eo = g_expert_out + ((size_t)(e * BB + b)) * UU;

  bool active = (wid < 7);   // 7 m-tiles of 16; warp 7 stages/stores only
  int R0 = wid * 16;

  // ldmatrix lane address bases (bytes)
  uint32_t aA_base =
      smb + ((A_OFF + (R0 + l15) * A_STR) << 2) + ((lane >> 4) << 4);
  // B x4 over n-tile pair: rows n = (lane>>4)*8 + (lane&7), k-half by bit 3
  uint32_t bW1_base = smb +
      ((W1_OFF + (((lane >> 4) << 3) + (lane & 7)) * 100) << 2) +
      (((lane >> 3) & 1) << 4);
  uint32_t bW2_base = smb +
      ((W2_OFF + (((lane >> 4) << 3) + (lane & 7)) * 100) << 2) +
      (((lane >> 3) & 1) << 4);

  for (int chunk = 0; chunk < 4; chunk++) {
    int l0 = chunk * 100;
    __syncthreads();  // prev chunk's A readers / h2s readers done

    // ---- stage A1 once: A[j][fp] = h2(x[2fp][gl], x[2fp+1][gl]), gl=l0-6+j
    for (int i = tid; i < 32 * 114; i += 256) {
      int fp = i / 114, j = i - fp * 114;
      int gl = l0 - 6 + j;
      float v0 = 0.f, v1 = 0.f;
      if (gl >= 0 && gl < LL) {
        v0 = xb[(2 * fp) * LL + gl];
        v1 = xb[(2 * fp + 1) * LL + gl];
      }
      smu[A_OFF + j * A_STR + fp] = pack_h2(v0, v1);
    }
    __syncthreads();

    // ---- conv1 MMA: kt = (k 0..2, fg 0..3); A row-shift = k ----
    float C1[8][4];
#pragma unroll
    for (int nt = 0; nt < 8; nt++)
#pragma unroll
      for (int j = 0; j < 4; j++) C1[nt][j] = 0.f;

    if (active) {
#pragma unroll
      for (int k = 0; k < 3; k++) {
#pragma unroll
        for (int fg = 0; fg < 4; fg++) {
          uint32_t a0, a1, a2, a3;
          ldsm4(a0, a1, a2, a3, aA_base + k * (A_STR * 4) + fg * 32);
#pragma unroll
          for (int np = 0; np < 4; np++) {
            uint32_t r0, r1, r2, r3;
            ldsm4(r0, r1, r2, r3,
                  bW1_base + np * 6400 + (k * 4 + fg) * 32);
            mma_f16(C1[2 * np], a0, a1, a2, a3, r0, r1);
            mma_f16(C1[2 * np + 1], a0, a1, a2, a3, r2, r3);
          }
        }
      }
    }
    __syncthreads();  // conv1 A reads done before epi1 overwrites A

    // ---- epilogue 1: A2[r][cp] = h2(relu(D1+b1)), single copy ----
    if (active) {
      int rA = R0 + gid, rB = rA + 8;
      bool mA = (chunk > 0) || (rA >= 4);  // causal: l1 = l0-4+r >= 0
#pragma unroll
      for (int nt = 0; nt < 8; nt++) {
        int cA = nt * 8 + 2 * tig;
        float v0 = fmaxf(C1[nt][0] + b1s[cA], 0.f);
        float v1 = fmaxf(C1[nt][1] + b1s[cA + 1], 0.f);
        float v2 = fmaxf(C1[nt][2] + b1s[cA], 0.f);
        float v3 = fmaxf(C1[nt][3] + b1s[cA + 1], 0.f);
        if (!mA) { v0 = 0.f; v1 = 0.f; }
        int cp = nt * 4 + tig;
        smu[A_OFF + rA * A_STR + cp] = pack_h2(v0, v1);
        smu[A_OFF + rB * A_STR + cp] = pack_h2(v2, v3);
      }
    }
    __syncthreads();

    // ---- conv2 MMA (A row-shift = 2k) + epilogue 2 ----
    if (active) {
      float C2[2][4];
#pragma unroll
      for (int nt = 0; nt < 2; nt++)
#pragma unroll
        for (int j = 0; j < 4; j++) C2[nt][j] = 0.f;
#pragma unroll
      for (int k = 0; k < 3; k++) {
#pragma unroll
        for (int fg = 0; fg < 4; fg++) {
          uint32_t a0, a1, a2, a3;
          ldsm4(a0, a1, a2, a3, aA_base + k * (2 * A_STR * 4) + fg * 32);
          uint32_t r0, r1, r2, r3;
          ldsm4(r0, r1, r2, r3, bW2_base + (k * 4 + fg) * 32);
          mma_f16(C2[0], a0, a1, a2, a3, r0, r1);
          mma_f16(C2[1], a0, a1, a2, a3, r2, r3);
        }
      }
      int mA = R0 + gid, mB = mA + 8;
#pragma unroll
      for (int nt = 0; nt < 2; nt++) {
        int cA = nt * 8 + 2 * tig;
        float v0 = fmaxf(C2[nt][0] + b2s[cA], 0.f);
        float v1 = fmaxf(C2[nt][1] + b2s[cA + 1], 0.f);
        float v2 = fmaxf(C2[nt][2] + b2s[cA], 0.f);
        float v3 = fmaxf(C2[nt][3] + b2s[cA + 1], 0.f);
        if (mA < 100) {
          sm[H2S_OFF + cA * 100 + mA] = v0;
          sm[H2S_OFF + (cA + 1) * 100 + mA] = v1;
        }
        if (mB < 100) {
          sm[H2S_OFF + cA * 100 + mB] = v2;
          sm[H2S_OFF + (cA + 1) * 100 + mB] = v3;
        }
      }
    }
    __syncthreads();

    // ---- store: +expert_bias, relu, coalesced ----
    for (int i = tid; i < C2C * 100; i += 256) {
      int c2 = i / 100, m = i - c2 * 100;
      int u = c2 * LL + l0 + m;
      eo[u] = fmaxf(sm[H2S_OFF + i] + ebp[u], 0.f);
    }
  }
}

// ---------------------------------------------------------------------------
// Gates: block = (8 batches, seg of 6400). Warp = (t, f-half).
// ---------------------------------------------------------------------------
__global__ void __launch_bounds__(256) gates_kernel(
    const float* __restrict__ x, const float* __restrict__ gk) {
  __shared__ float xs[8][1288];
  __shared__ float part[8][64];
  int tid = threadIdx.x;
  int b0 = blockIdx.x * 8, seg = blockIdx.y;
  int w = tid >> 5, lane = tid & 31;
  int t = w >> 1, half = w & 1;

  float acc[8][8];
#pragma unroll
  for (int bi = 0; bi < 8; bi++)
#pragma unroll
    for (int e2 = 0; e2 < 8; e2++) acc[bi][e2] = 0.f;

  for (int c = 0; c < 5; c++) {
    __syncthreads();
    for (int i = tid; i < 8 * 1280; i += 256) {
      int bi = i / 1280, j = i - bi * 1280;
      xs[bi][j] = x[(size_t)(b0 + bi) * FL + seg * 6400 + c * 1280 + j];
    }
    __syncthreads();
    const float4* gp = reinterpret_cast<const float4*>(
        gk + ((size_t)t * FL + seg * 6400 + c * 1280) * EE);
    int fb = half * 640;
#pragma unroll 2
    for (int ii = 0; ii < 20; ii++) {
      int f = fb + ii * 32 + lane;
      float4 ga = gp[2 * f];
      float4 gb2 = gp[2 * f + 1];
#pragma unroll
      for (int bi = 0; bi < 8; bi++) {
        float xv = xs[bi][f];
        acc[bi][0] += xv * ga.x;  acc[bi][1] += xv * ga.y;
        acc[bi][2] += xv * ga.z;  acc[bi][3] += xv * ga.w;
        acc[bi][4] += xv * gb2.x; acc[bi][5] += xv * gb2.y;
        acc[bi][6] += xv * gb2.z; acc[bi][7] += xv * gb2.w;
      }
    }
  }
#pragma unroll
  for (int bi = 0; bi < 8; bi++)
#pragma unroll
    for (int e2 = 0; e2 < 8; e2++) {
      float v = acc[bi][e2];
      v += __shfl_xor_sync(0xffffffffu, v, 16);
      v += __shfl_xor_sync(0xffffffffu, v, 8);
      v += __shfl_xor_sync(0xffffffffu, v, 4);
      v += __shfl_xor_sync(0xffffffffu, v, 2);
      v += __shfl_xor_sync(0xffffffffu, v, 1);
      acc[bi][e2] = v;
    }
  if (lane == 0) {
#pragma unroll
    for (int bi = 0; bi < 8; bi++)
#pragma unroll
      for (int e2 = 0; e2 < 8; e2++) part[w][bi * 8 + e2] = acc[bi][e2];
  }
  __syncthreads();
  {
    int t2 = tid >> 6, rem = tid & 63;
    int bi = rem >> 3, e2 = rem & 7;
    float s = part[t2 * 2][rem] + part[t2 * 2 + 1][rem];
    g_part[(((size_t)seg * TT + t2) * BB + b0 + bi) * EE + e2] = s;
  }
}

// ---------------------------------------------------------------------------
__global__ void __launch_bounds__(256) finalize_gates(
    const float* __restrict__ gbias) {
  int gid = blockIdx.x * 256 + threadIdx.x;
  if (gid >= TT * BB) return;
  int t = gid >> 9, b = gid & 511;
  float v[8];
  float mx = -1e30f;
#pragma unroll
  for (int e = 0; e < 8; e++) {
    float s = gbias[t * 8 + e];
#pragma unroll
    for (int sg = 0; sg < 4; sg++)
      s += g_part[(((size_t)sg * TT + t) * BB + b) * EE + e];
    v[e] = s;
    mx = fmaxf(mx, s);
  }
  float sum = 0.f;
#pragma unroll
  for (int e = 0; e < 8; e++) { v[e] = expf(v[e] - mx); sum += v[e]; }
  float inv = 1.f / sum;
#pragma unroll
  for (int e = 0; e < 8; e++)
    g_gates[((size_t)t * BB + b) * EE + e] = v[e] * inv;
}

// ---------------------------------------------------------------------------
__global__ void __launch_bounds__(256) mix_kernel(
    const float* __restrict__ tbias, float* __restrict__ out) {
  __shared__ float gsh[TT * EE];
  int b = blockIdx.x;
  int tid = threadIdx.x;
  if (tid < TT * EE)
    gsh[tid] = g_gates[((size_t)(tid >> 3) * BB + b) * EE + (tid & 7)];
  __syncthreads();
  int u4 = (blockIdx.y * 256 + tid) * 4;
  if (u4 >= UU) return;

  float4 a[TT];
#pragma unroll
  for (int t = 0; t < TT; t++) {
    float tb = tbias[t];
    a[t] = make_float4(tb, tb, tb, tb);
  }
#pragma unroll
  for (int e = 0; e < EE; e++) {
    float4 v = *reinterpret_cast<const float4*>(
        g_expert_out + ((size_t)(e * BB + b)) * UU + u4);
#pragma unroll
    for (int t = 0; t < TT; t++) {
      float g = gsh[t * 8 + e];
      a[t].x += g * v.x;
      a[t].y += g * v.y;
      a[t].z += g * v.z;
      a[t].w += g * v.w;
    }
  }
#pragma unroll
  for (int t = 0; t < TT; t++)
    *reinterpret_cast<float4*>(out + ((size_t)(t * BB + b)) * UU + u4) = a[t];
}

// ---------------------------------------------------------------------------
extern "C" void kernel_launch(void* const* d_in, const int* in_sizes, int n_in,
                              void* d_out, int out_size) {
  const float* x  = (const float*)d_in[0];
  const float* w1 = (const float*)d_in[1];
  const float* b1 = (const float*)d_in[2];
  const float* w2 = (const float*)d_in[3];
  const float* b2 = (const float*)d_in[4];
  const float* eb = (const float*)d_in[5];
  const float* gk = (const float*)d_in[6];
  const float* gb = (const float*)d_in[7];
  const float* tb = (const float*)d_in[8];
  float* out = (float*)d_out;

  cudaFuncSetAttribute(expert_mma_kernel,
                       cudaFuncAttributeMaxDynamicSharedMemorySize, SMEM_BYTES);

  // two launches (b halves) so ncu's -s 5 lands on an expert launch
  expert_mma_kernel<<<EE * (BB / 2), 256, SMEM_BYTES>>>(x, w1, b1, w2, b2, eb, 0);
  expert_mma_kernel<<<EE * (BB / 2), 256, SMEM_BYTES>>>(x, w1, b1, w2, b2, eb,
                                                        BB / 2);
  gates_kernel<<<dim3(BB / 8, 4), 256>>>(x, gk);
  finalize_gates<<<8, 256>>>(gb);
  mix_kernel<<<dim3(BB, 7), 256>>>(tb, out);
}